// round 15
// baseline (speedup 1.0000x reference)
#include <cuda_runtime.h>
#include <cuda_bf16.h>
#include <math.h>

#define IMG_H 768
#define IMG_W 768
#define IMG_B 16
#define NPIXD 9437184.0
#define TILE 32
#define RAW_W 53            /* cols gx0-12 .. gx0+40 */
#define RAW_H 50            /* rows gy0-9  .. gy0+40 */
#define H3STR 33
#define H1ROWS 38
#define BINS 4096
#define NACC 15
#define NSTRIPE 32
#define GRID_X 24
#define GRID_Y 24
#define NBLOCKS (GRID_X*GRID_Y*IMG_B)
#define SMEM_FLOATS 15408   /* 61632 bytes */

/* smem float offsets */
#define O_XI   0
#define O_YP   2650
#define O_U    5300
#define O_H3I  7950
#define O_H3P  9600
#define O_H3U  11250
#define O_H1I  12900
#define O_H1P  14154

__device__ double       g_acc[NSTRIPE*NACC];
__device__ unsigned int g_hist[2*BINS];   /* [0,BINS)=yp(body)  [BINS,2BINS)=x_i(body) */
__device__ unsigned int g_done;

#define G3_INIT {0.00147946f,0.00380425f,0.00875347f,0.01802342f,0.03320773f,\
                 0.05475029f,0.08077532f,0.10663899f,0.12597909f,0.13317599f,\
                 0.12597909f,0.10663899f,0.08077532f,0.05475029f,0.03320773f,\
                 0.01802342f,0.00875347f,0.00380425f,0.00147946f}
#define G1_INIT {0.00443305f,0.05400558f,0.24203624f,0.39905030f,0.24203624f,\
                 0.05400558f,0.00443305f}

__global__ void __launch_bounds__(256, 3) k_main(
    const float* __restrict__ ypred, const float* __restrict__ npred,
    const float* __restrict__ xi,    const float* __restrict__ xmid,
    const float* __restrict__ wmap,  const float* __restrict__ nsyn,
    float* __restrict__ out)
{
    const float G3W[19] = G3_INIT;
    const float G1W[7]  = G1_INIT;

    extern __shared__ float sm[];
    float* s_xi = sm + O_XI;
    float* s_yp = sm + O_YP;
    float* s_u  = sm + O_U;
    float* h3i  = sm + O_H3I;
    float* h3p  = sm + O_H3P;
    float* h3u  = sm + O_H3U;
    float* h1i  = sm + O_H1I;
    float* h1p  = sm + O_H1P;

    __shared__ float s_part[NACC][8];
    __shared__ unsigned int s_islast;

    const int tid = threadIdx.x;

    const int gx0 = blockIdx.x * TILE;
    const int gy0 = blockIdx.y * TILE;
    const size_t base = (size_t)blockIdx.z * (IMG_H*IMG_W);
    const bool xsafe = (blockIdx.x > 0) && (blockIdx.x < GRID_X-1);

    /* ---- phase 1: load halo tiles; U = yp - 0.3 xi - 0.7 xm ---- */
    for (int idx = tid; idx < RAW_H*14; idx += 256) {
        int row = idx / 14, q = idx - row*14;
        int sc = q*4;
        int gy = gy0 + row - 9;
        float ai[4] = {0.f,0.f,0.f,0.f};
        float ap[4] = {0.f,0.f,0.f,0.f};
        float am[4] = {0.f,0.f,0.f,0.f};
        if ((unsigned)gy < IMG_H) {
            int gxs = gx0 - 12 + sc;
            size_t g = base + (size_t)gy*IMG_W + gxs;
            if (xsafe) {
                float4 vi = *(const float4*)(xi+g);
                float4 vp = *(const float4*)(ypred+g);
                float4 vm = *(const float4*)(xmid+g);
                ai[0]=vi.x; ai[1]=vi.y; ai[2]=vi.z; ai[3]=vi.w;
                ap[0]=vp.x; ap[1]=vp.y; ap[2]=vp.z; ap[3]=vp.w;
                am[0]=vm.x; am[1]=vm.y; am[2]=vm.z; am[3]=vm.w;
            } else {
#pragma unroll
                for (int e = 0; e < 4; e++) {
                    if ((unsigned)(gxs+e) < IMG_W) {
                        ai[e] = xi[g+e]; ap[e] = ypred[g+e]; am[e] = xmid[g+e];
                    }
                }
            }
        }
        int o = row*RAW_W + sc;
#pragma unroll
        for (int e = 0; e < 4; e++) {
            if (sc+e < RAW_W) {
                s_xi[o+e] = ai[e];
                s_yp[o+e] = ap[e];
                s_u[o+e]  = ap[e] - 0.3f*ai[e] - 0.7f*am[e];
            }
        }
    }
    __syncthreads();

    /* ---- phase 2: horizontal convs (dense mapping) ---- */
    {
        const int row = tid >> 2, seg = tid & 3;
        if (row < RAW_H) {
            const int bi = row*RAW_W + seg*8 + 3;
            const int bo = row*H3STR + seg*8;
            float w[26];
#pragma unroll
            for (int j = 0; j < 26; j++) w[j] = s_xi[bi+j];
#pragma unroll
            for (int i = 0; i < 8; i++) {
                float a = 0.f;
#pragma unroll
                for (int k = 0; k < 19; k++) a = fmaf(w[i+k], G3W[k], a);
                h3i[bo+i] = a;
            }
#pragma unroll
            for (int j = 0; j < 26; j++) w[j] = s_yp[bi+j];
#pragma unroll
            for (int i = 0; i < 8; i++) {
                float a = 0.f;
#pragma unroll
                for (int k = 0; k < 19; k++) a = fmaf(w[i+k], G3W[k], a);
                h3p[bo+i] = a;
            }
#pragma unroll
            for (int j = 0; j < 26; j++) w[j] = s_u[bi+j];
#pragma unroll
            for (int i = 0; i < 8; i++) {
                float a = 0.f;
#pragma unroll
                for (int k = 0; k < 19; k++) a = fmaf(w[i+k], G3W[k], a);
                h3u[bo+i] = a;
            }
        }
        if (row < H1ROWS) {
            const int bi = (row+6)*RAW_W + seg*8 + 9;
            const int bo = row*H3STR + seg*8;
            float u[14];
#pragma unroll
            for (int j = 0; j < 14; j++) u[j] = s_xi[bi+j];
#pragma unroll
            for (int i = 0; i < 8; i++) {
                float a = 0.f;
#pragma unroll
                for (int k = 0; k < 7; k++) a = fmaf(u[i+k], G1W[k], a);
                h1i[bo+i] = a;
            }
#pragma unroll
            for (int j = 0; j < 14; j++) u[j] = s_yp[bi+j];
#pragma unroll
            for (int i = 0; i < 8; i++) {
                float a = 0.f;
#pragma unroll
                for (int k = 0; k < 7; k++) a = fmaf(u[i+k], G1W[k], a);
                h1p[bo+i] = a;
            }
        }
    }
    __syncthreads();

    /* ---- phase 3: prefetch phase-4 global operands, then vertical convs ---- */
    const int c  = tid & 31;
    const int r0 = (tid >> 5) << 2;

    /* issue DRAM loads NOW; ~1000+ cycles of conv work below hides the latency */
    float pwv[4], pnv[4], psv[4];
#pragma unroll
    for (int j = 0; j < 4; j++) {
        size_t g = base + (size_t)(gy0 + r0 + j)*IMG_W + (gx0 + c);
        pwv[j] = wmap[g]; pnv[j] = npred[g]; psv[j] = nsyn[g];
    }

    float A4[4], B4[4], C4[4];
    {
        float win[22];
#pragma unroll
        for (int k = 0; k < 22; k++) win[k] = h3u[(r0+k)*H3STR + c];
        float a0=0.f,a1=0.f,a2=0.f,a3=0.f;
#pragma unroll
        for (int k = 0; k < 19; k++) { float w=G3W[k];
            a0=fmaf(win[k],w,a0); a1=fmaf(win[k+1],w,a1);
            a2=fmaf(win[k+2],w,a2); a3=fmaf(win[k+3],w,a3); }
        A4[0]=a0; A4[1]=a1; A4[2]=a2; A4[3]=a3;
#pragma unroll
        for (int k = 0; k < 22; k++) win[k] = h3i[(r0+k)*H3STR + c];
        a0=a1=a2=a3=0.f;
#pragma unroll
        for (int k = 0; k < 19; k++) { float w=G3W[k];
            a0=fmaf(win[k],w,a0); a1=fmaf(win[k+1],w,a1);
            a2=fmaf(win[k+2],w,a2); a3=fmaf(win[k+3],w,a3); }
        B4[0]=-a0; B4[1]=-a1; B4[2]=-a2; B4[3]=-a3;
#pragma unroll
        for (int k = 0; k < 22; k++) win[k] = h3p[(r0+k)*H3STR + c];
        a0=a1=a2=a3=0.f;
#pragma unroll
        for (int k = 0; k < 19; k++) { float w=G3W[k];
            a0=fmaf(win[k],w,a0); a1=fmaf(win[k+1],w,a1);
            a2=fmaf(win[k+2],w,a2); a3=fmaf(win[k+3],w,a3); }
        C4[0]=-a0; C4[1]=-a1; C4[2]=-a2; C4[3]=-a3;
    }
    {
        float win[10];
#pragma unroll
        for (int k = 0; k < 10; k++) win[k] = h1i[(r0+k)*H3STR + c];
        float a0=0.f,a1=0.f,a2=0.f,a3=0.f;
#pragma unroll
        for (int k = 0; k < 7; k++) { float w=G1W[k];
            a0=fmaf(win[k],w,a0); a1=fmaf(win[k+1],w,a1);
            a2=fmaf(win[k+2],w,a2); a3=fmaf(win[k+3],w,a3); }
        B4[0]+=a0; B4[1]+=a1; B4[2]+=a2; B4[3]+=a3;
#pragma unroll
        for (int k = 0; k < 10; k++) win[k] = h1p[(r0+k)*H3STR + c];
        a0=a1=a2=a3=0.f;
#pragma unroll
        for (int k = 0; k < 7; k++) { float w=G1W[k];
            a0=fmaf(win[k],w,a0); a1=fmaf(win[k+1],w,a1);
            a2=fmaf(win[k+2],w,a2); a3=fmaf(win[k+3],w,a3); }
        C4[0]+=a0; C4[1]+=a1; C4[2]+=a2; C4[3]+=a3;
    }

    /* ---- phase 4: stencils (6-row shared loads) + pointwise + reductions ---- */
    float gxi4[4], gyi4[4], lapi4[4], xv4[4];
    {
        float xr[6][3];
#pragma unroll
        for (int k = 0; k < 6; k++) {
            int pp = (r0+8+k)*RAW_W + (c+11);
            xr[k][0]=s_xi[pp]; xr[k][1]=s_xi[pp+1]; xr[k][2]=s_xi[pp+2];
        }
#pragma unroll
        for (int j = 0; j < 4; j++) {
            float x00=xr[j][0],  x01=xr[j][1],  x02=xr[j][2];
            float x10=xr[j+1][0],x11=xr[j+1][1],x12=xr[j+1][2];
            float x20=xr[j+2][0],x21=xr[j+2][1],x22=xr[j+2][2];
            gxi4[j]  = (x02-x00) + 2.f*(x12-x10) + (x22-x20);
            gyi4[j]  = (x20-x00) + 2.f*(x21-x01) + (x22-x02);
            lapi4[j] = x01 + x21 + x10 + x12 - 4.f*x11;
            xv4[j]   = x11;
        }
    }
    float yr[6][3];
#pragma unroll
    for (int k = 0; k < 6; k++) {
        int pp = (r0+8+k)*RAW_W + (c+11);
        yr[k][0]=s_yp[pp]; yr[k][1]=s_yp[pp+1]; yr[k][2]=s_yp[pp+2];
    }

    float a_rc=0.f,a_nb=0.f,a_sxi=0.f,a_syp=0.f,a_ex=0.f,a_ey=0.f;
    float a_ntex=0.f,a_tex=0.f,a_nf=0.f,a_hf=0.f,a_ic=0.f;
    float a_nfb=0.f,a_lf=0.f,a_mid=0.f,a_syn=0.f;

#pragma unroll
    for (int j = 0; j < 4; j++) {
        float wv = pwv[j], nv = pnv[j], sv = psv[j];

        float y00=yr[j][0],  y01=yr[j][1],  y02=yr[j][2];
        float y10=yr[j+1][0],y11=yr[j+1][1],y12=yr[j+1][2];
        float y20=yr[j+2][0],y21=yr[j+2][1],y22=yr[j+2][2];

        float gxp_ = (y02-y00) + 2.f*(y12-y10) + (y22-y20);
        float gyp_ = (y20-y00) + 2.f*(y21-y01) + (y22-y02);
        float lapp = y01 + y21 + y10 + y12 - 4.f*y11;
        float gxi_ = gxi4[j], gyi_ = gyi4[j], lapi = lapi4[j];
        float xv = xv4[j], pv = y11;

        a_rc += fabsf(pv*wv - xv*wv);
        float gmi = sqrtf(fmaf(gxi_,gxi_, fmaf(gyi_,gyi_, 1e-8f)));
        float gmp = sqrtf(fmaf(gxp_,gxp_, fmaf(gyp_,gyp_, 1e-8f)));
        a_ex += fabsf(gxp_-gxi_);
        a_ey += fabsf(gyp_-gyi_);
        bool body = (xv > 0.15f) && (xv < 0.85f);
        bool flat = gmi < 0.03f;
        bool tex  = (gmi > 0.03f) && (gmi < 0.5f);
        if (body) {
            a_nb += 1.f; a_sxi += xv; a_syp += pv;
            int bp = (int)(pv * (float)BINS); bp = bp < 0 ? 0 : (bp > BINS-1 ? BINS-1 : bp);
            int bx = (int)(xv * (float)BINS); bx = bx < 0 ? 0 : (bx > BINS-1 ? BINS-1 : bx);
            atomicAdd(&g_hist[bp], 1u);
            atomicAdd(&g_hist[BINS + bx], 1u);
        }
        if (tex) { a_ntex += 1.f; a_tex += fabsf(gmp - gmi); }
        if (flat) {
            a_nf += 1.f;
            a_hf += fabsf(fabsf(lapp) - 0.3f*fabsf(lapi));
            a_ic += fmaxf(gmp - 2.0f*gmi, 0.f);
            if (body) {
                a_nfb += 1.f;
                a_lf  += fabsf(A4[j]);
                a_mid += fabsf(fabsf(C4[j]) - 0.3f*fabsf(B4[j]));
                a_syn += fabsf(nv - sv);
            }
        }
    }

    /* block reduction: warp shuffle -> plain STS partials -> 15-thread sum -> striped global */
    {
        float vals[NACC] = {a_rc,a_nb,a_sxi,a_syp,a_ex,a_ey,a_ntex,a_tex,
                            a_nf,a_hf,a_ic,a_nfb,a_lf,a_mid,a_syn};
        const int wid = tid >> 5;
#pragma unroll
        for (int i = 0; i < NACC; i++) {
            float v = vals[i];
#pragma unroll
            for (int off = 16; off; off >>= 1) v += __shfl_down_sync(0xffffffffu, v, off);
            if ((tid & 31) == 0) s_part[i][wid] = v;
        }
    }
    __syncthreads();
    {
        const int bid = blockIdx.x + blockIdx.y*GRID_X + blockIdx.z*(GRID_X*GRID_Y);
        const int stripe = bid & (NSTRIPE-1);
        if (tid < NACC) {
            float s = 0.f;
#pragma unroll
            for (int w = 0; w < 8; w++) s += s_part[tid][w];
            atomicAdd(&g_acc[stripe*NACC + tid], (double)s);
        }
    }

    /* ---- last-block finalize ---- */
    __threadfence();
    if (tid == 0) {
        unsigned int prev = atomicAdd(&g_done, 1u);
        s_islast = (prev == NBLOCKS-1) ? 1u : 0u;
    }
    __syncthreads();
    if (!s_islast) return;
    __threadfence();

    {
        __shared__ unsigned int pre_yp[257], pre_xi2[257];
        __shared__ float qv[8];
        __shared__ float s_fr[2];
        __shared__ double s_tot[NACC];
        const int t = tid;

        if (t < NACC) {
            double s = 0.0;
#pragma unroll
            for (int w = 0; w < NSTRIPE; w++) s += g_acc[w*NACC + t];
            s_tot[t] = s;
        }

        unsigned int syp = 0, sxi = 0;
#pragma unroll
        for (int i = 0; i < 16; i++) {
            syp += g_hist[t*16 + i];
            sxi += g_hist[BINS + t*16 + i];
        }
        pre_yp[t] = syp; pre_xi2[t] = sxi;
        if (t < 8) qv[t] = 0.f;
        __syncthreads();
        if (t == 0) {
            unsigned int run = 0;
            for (int i = 0; i < 256; i++) { unsigned int x = pre_yp[i]; pre_yp[i] = run; run += x; }
            pre_yp[256] = run;
            run = 0;
            for (int i = 0; i < 256; i++) { unsigned int x = pre_xi2[i]; pre_xi2[i] = run; run += x; }
            pre_xi2[256] = run;
        }
        __syncthreads();

        long long n = (long long)pre_xi2[256];
        long long ranks[4] = {0,0,0,0};
        float fr25 = 0.f, fr75 = 0.f;
        if (n > 0) {
            float pos25 = 0.25f * (float)(n-1);
            float pos75 = 0.75f * (float)(n-1);
            fr25 = pos25 - floorf(pos25);
            fr75 = pos75 - floorf(pos75);
            ranks[0] = (long long)floorf(pos25);
            ranks[1] = (long long)ceilf(pos25);
            ranks[2] = (long long)floorf(pos75);
            ranks[3] = (long long)ceilf(pos75);
        }
        if (t == 0) { s_fr[0] = fr25; s_fr[1] = fr75; }
        {
            long long cum = (long long)pre_yp[t];
            for (int i = 0; i < 16; i++) {
                unsigned int cnt = g_hist[t*16 + i];
#pragma unroll
                for (int j = 0; j < 4; j++) {
                    if (ranks[j] >= cum && ranks[j] < cum + (long long)cnt)
                        qv[j] = ((float)(t*16+i) + ((float)(ranks[j]-cum) + 0.5f)/(float)cnt) * (1.0f/(float)BINS);
                }
                cum += cnt;
            }
        }
        {
            long long cum = (long long)pre_xi2[t];
            for (int i = 0; i < 16; i++) {
                unsigned int cnt = g_hist[BINS + t*16 + i];
#pragma unroll
                for (int j = 0; j < 4; j++) {
                    if (ranks[j] >= cum && ranks[j] < cum + (long long)cnt)
                        qv[4+j] = ((float)(t*16+i) + ((float)(ranks[j]-cum) + 0.5f)/(float)cnt) * (1.0f/(float)BINS);
                }
                cum += cnt;
            }
        }
        __syncthreads();

        if (t == 0) {
            double nb      = s_tot[1];
            double rc      = s_tot[0] / NPIXD;
            double edge    = (s_tot[4] + s_tot[5]) / NPIXD;
            double mean_in = s_tot[2] / fmax(nb, 1.0);
            double mean_pr = s_tot[3] / fmax(nb, 1.0);
            float f25 = s_fr[0], f75 = s_fr[1];
            float q25p = qv[0]*(1.f-f25) + qv[1]*f25;
            float q75p = qv[2]*(1.f-f75) + qv[3]*f75;
            float q25i = qv[4]*(1.f-f25) + qv[5]*f25;
            float q75i = qv[6]*(1.f-f75) + qv[7]*f75;
            double dm   = mean_pr - mean_in;
            double dq25 = (double)q25p - (double)q25i;
            double dq75 = (double)q75p - (double)q75i;
            double hu   = dm*dm + 0.5*(dq25*dq25 + dq75*dq75);
            double loss_hu  = (nb > 4096.0) ? hu : 0.0;
            double ntex = s_tot[6];
            double loss_tex = (ntex > 100.0) ? s_tot[7]/fmax(ntex,1.0) : 0.0;
            double nf   = s_tot[8];
            double loss_hf  = (nf > 100.0) ? s_tot[9]/fmax(nf,1.0)  : 0.0;
            double loss_ic  = (nf > 100.0) ? s_tot[10]/fmax(nf,1.0) : 0.0;
            double nfb  = s_tot[11];
            double loss_lf  = (nfb > 100.0) ? s_tot[12]/fmax(nfb,1.0) : 0.0;
            double loss_mid = (nfb > 100.0) ? s_tot[13]/fmax(nfb,1.0) : 0.0;
            double loss_syn = (nfb > 100.0) ? s_tot[14]/fmax(nfb,1.0) : 0.0;
            double total = 2.0*rc + 1.5*loss_hu + 1.0*edge + 0.8*loss_tex
                         + 1.5*loss_hf + 0.8*loss_mid + 0.6*loss_lf
                         + 1.0*loss_syn + 0.8*loss_ic;
            out[0] = (float)total;
        }
        __syncthreads();

        /* self-clean for next graph replay */
        for (int i = t; i < 2*BINS; i += 256) g_hist[i] = 0u;
        for (int i = t; i < NSTRIPE*NACC; i += 256) g_acc[i] = 0.0;
        if (t == 0)  g_done = 0u;
    }
}

extern "C" void kernel_launch(void* const* d_in, const int* in_sizes, int n_in,
                              void* d_out, int out_size)
{
    (void)in_sizes; (void)n_in; (void)out_size;
    const float* ypred = (const float*)d_in[0];
    const float* npred = (const float*)d_in[1];
    const float* xi    = (const float*)d_in[2];
    /* d_in[3] = x_ip1 unused by the reference */
    const float* xmid  = (const float*)d_in[4];
    const float* wmap  = (const float*)d_in[5];
    const float* nsyn  = (const float*)d_in[6];

    cudaFuncSetAttribute(k_main, cudaFuncAttributeMaxDynamicSharedMemorySize,
                         SMEM_FLOATS * (int)sizeof(float));
    dim3 grid(GRID_X, GRID_Y, IMG_B);
    k_main<<<grid, 256, SMEM_FLOATS * sizeof(float)>>>(
        ypred, npred, xi, xmid, wmap, nsyn, (float*)d_out);
}

// round 16
// speedup vs baseline: 1.8122x; 1.8122x over previous
#include <cuda_runtime.h>
#include <cuda_bf16.h>
#include <math.h>

#define IMG_H 768
#define IMG_W 768
#define IMG_B 16
#define NPIXD 9437184.0
#define TILE 32
#define RAW_W 53            /* cols gx0-12 .. gx0+40 */
#define RAW_H 50            /* rows gy0-9  .. gy0+40 */
#define H3STR 33
#define H1ROWS 38
#define BINS 4096
#define NACC 15
#define NSTRIPE 32
#define GRID_X 24
#define GRID_Y 24
#define NBLOCKS (GRID_X*GRID_Y*IMG_B)
#define SMEM_FLOATS 15408   /* 61632 bytes */

/* smem float offsets */
#define O_XI   0
#define O_YP   2650
#define O_U    5300
#define O_H3I  7950
#define O_H3P  9600
#define O_H3U  11250
#define O_H1I  12900
#define O_H1P  14154

__device__ double       g_acc[NSTRIPE*NACC];
__device__ unsigned int g_hist[2*BINS];   /* [0,BINS)=yp(body)  [BINS,2BINS)=x_i(body), 4x subsampled */
__device__ unsigned int g_done;

#define G3_INIT {0.00147946f,0.00380425f,0.00875347f,0.01802342f,0.03320773f,\
                 0.05475029f,0.08077532f,0.10663899f,0.12597909f,0.13317599f,\
                 0.12597909f,0.10663899f,0.08077532f,0.05475029f,0.03320773f,\
                 0.01802342f,0.00875347f,0.00380425f,0.00147946f}
#define G1_INIT {0.00443305f,0.05400558f,0.24203624f,0.39905030f,0.24203624f,\
                 0.05400558f,0.00443305f}

__device__ __forceinline__ float fast_sqrtf(float x) {
    float r;
    asm("sqrt.approx.f32 %0, %1;" : "=f"(r) : "f"(x));
    return r;
}

__global__ void __launch_bounds__(256, 3) k_main(
    const float* __restrict__ ypred, const float* __restrict__ npred,
    const float* __restrict__ xi,    const float* __restrict__ xmid,
    const float* __restrict__ wmap,  const float* __restrict__ nsyn,
    float* __restrict__ out)
{
    const float G3W[19] = G3_INIT;
    const float G1W[7]  = G1_INIT;

    extern __shared__ float sm[];
    float* s_xi = sm + O_XI;
    float* s_yp = sm + O_YP;
    float* s_u  = sm + O_U;
    float* h3i  = sm + O_H3I;
    float* h3p  = sm + O_H3P;
    float* h3u  = sm + O_H3U;
    float* h1i  = sm + O_H1I;
    float* h1p  = sm + O_H1P;

    __shared__ float s_part[NACC][8];
    __shared__ unsigned int s_islast;

    const int tid = threadIdx.x;

    const int gx0 = blockIdx.x * TILE;
    const int gy0 = blockIdx.y * TILE;
    const size_t base = (size_t)blockIdx.z * (IMG_H*IMG_W);
    const bool xsafe = (blockIdx.x > 0) && (blockIdx.x < GRID_X-1);

    /* ---- phase 1: load halo tiles; U = yp - 0.3 xi - 0.7 xm ---- */
    for (int idx = tid; idx < RAW_H*14; idx += 256) {
        int row = idx / 14, q = idx - row*14;
        int sc = q*4;
        int gy = gy0 + row - 9;
        float ai[4] = {0.f,0.f,0.f,0.f};
        float ap[4] = {0.f,0.f,0.f,0.f};
        float am[4] = {0.f,0.f,0.f,0.f};
        if ((unsigned)gy < IMG_H) {
            int gxs = gx0 - 12 + sc;
            size_t g = base + (size_t)gy*IMG_W + gxs;
            if (xsafe) {
                float4 vi = *(const float4*)(xi+g);
                float4 vp = *(const float4*)(ypred+g);
                float4 vm = *(const float4*)(xmid+g);
                ai[0]=vi.x; ai[1]=vi.y; ai[2]=vi.z; ai[3]=vi.w;
                ap[0]=vp.x; ap[1]=vp.y; ap[2]=vp.z; ap[3]=vp.w;
                am[0]=vm.x; am[1]=vm.y; am[2]=vm.z; am[3]=vm.w;
            } else {
#pragma unroll
                for (int e = 0; e < 4; e++) {
                    if ((unsigned)(gxs+e) < IMG_W) {
                        ai[e] = xi[g+e]; ap[e] = ypred[g+e]; am[e] = xmid[g+e];
                    }
                }
            }
        }
        int o = row*RAW_W + sc;
#pragma unroll
        for (int e = 0; e < 4; e++) {
            if (sc+e < RAW_W) {
                s_xi[o+e] = ai[e];
                s_yp[o+e] = ap[e];
                s_u[o+e]  = ap[e] - 0.3f*ai[e] - 0.7f*am[e];
            }
        }
    }
    __syncthreads();

    /* ---- phase 2: horizontal convs (dense mapping) ---- */
    {
        const int row = tid >> 2, seg = tid & 3;
        if (row < RAW_H) {
            const int bi = row*RAW_W + seg*8 + 3;
            const int bo = row*H3STR + seg*8;
            float w[26];
#pragma unroll
            for (int j = 0; j < 26; j++) w[j] = s_xi[bi+j];
#pragma unroll
            for (int i = 0; i < 8; i++) {
                float a = 0.f;
#pragma unroll
                for (int k = 0; k < 19; k++) a = fmaf(w[i+k], G3W[k], a);
                h3i[bo+i] = a;
            }
#pragma unroll
            for (int j = 0; j < 26; j++) w[j] = s_yp[bi+j];
#pragma unroll
            for (int i = 0; i < 8; i++) {
                float a = 0.f;
#pragma unroll
                for (int k = 0; k < 19; k++) a = fmaf(w[i+k], G3W[k], a);
                h3p[bo+i] = a;
            }
#pragma unroll
            for (int j = 0; j < 26; j++) w[j] = s_u[bi+j];
#pragma unroll
            for (int i = 0; i < 8; i++) {
                float a = 0.f;
#pragma unroll
                for (int k = 0; k < 19; k++) a = fmaf(w[i+k], G3W[k], a);
                h3u[bo+i] = a;
            }
        }
        if (row < H1ROWS) {
            const int bi = (row+6)*RAW_W + seg*8 + 9;
            const int bo = row*H3STR + seg*8;
            float u[14];
#pragma unroll
            for (int j = 0; j < 14; j++) u[j] = s_xi[bi+j];
#pragma unroll
            for (int i = 0; i < 8; i++) {
                float a = 0.f;
#pragma unroll
                for (int k = 0; k < 7; k++) a = fmaf(u[i+k], G1W[k], a);
                h1i[bo+i] = a;
            }
#pragma unroll
            for (int j = 0; j < 14; j++) u[j] = s_yp[bi+j];
#pragma unroll
            for (int i = 0; i < 8; i++) {
                float a = 0.f;
#pragma unroll
                for (int k = 0; k < 7; k++) a = fmaf(u[i+k], G1W[k], a);
                h1p[bo+i] = a;
            }
        }
    }
    __syncthreads();

    /* ---- phase 3: vertical convs -> A = G3*U, B = (G1-G3)*xi, C = (G1-G3)*yp ---- */
    const int c  = tid & 31;
    const int r0 = (tid >> 5) << 2;

    float A4[4], B4[4], C4[4];
    {
        float win[22];
#pragma unroll
        for (int k = 0; k < 22; k++) win[k] = h3u[(r0+k)*H3STR + c];
        float a0=0.f,a1=0.f,a2=0.f,a3=0.f;
#pragma unroll
        for (int k = 0; k < 19; k++) { float w=G3W[k];
            a0=fmaf(win[k],w,a0); a1=fmaf(win[k+1],w,a1);
            a2=fmaf(win[k+2],w,a2); a3=fmaf(win[k+3],w,a3); }
        A4[0]=a0; A4[1]=a1; A4[2]=a2; A4[3]=a3;
#pragma unroll
        for (int k = 0; k < 22; k++) win[k] = h3i[(r0+k)*H3STR + c];
        a0=a1=a2=a3=0.f;
#pragma unroll
        for (int k = 0; k < 19; k++) { float w=G3W[k];
            a0=fmaf(win[k],w,a0); a1=fmaf(win[k+1],w,a1);
            a2=fmaf(win[k+2],w,a2); a3=fmaf(win[k+3],w,a3); }
        B4[0]=-a0; B4[1]=-a1; B4[2]=-a2; B4[3]=-a3;
#pragma unroll
        for (int k = 0; k < 22; k++) win[k] = h3p[(r0+k)*H3STR + c];
        a0=a1=a2=a3=0.f;
#pragma unroll
        for (int k = 0; k < 19; k++) { float w=G3W[k];
            a0=fmaf(win[k],w,a0); a1=fmaf(win[k+1],w,a1);
            a2=fmaf(win[k+2],w,a2); a3=fmaf(win[k+3],w,a3); }
        C4[0]=-a0; C4[1]=-a1; C4[2]=-a2; C4[3]=-a3;
    }
    {
        float win[10];
#pragma unroll
        for (int k = 0; k < 10; k++) win[k] = h1i[(r0+k)*H3STR + c];
        float a0=0.f,a1=0.f,a2=0.f,a3=0.f;
#pragma unroll
        for (int k = 0; k < 7; k++) { float w=G1W[k];
            a0=fmaf(win[k],w,a0); a1=fmaf(win[k+1],w,a1);
            a2=fmaf(win[k+2],w,a2); a3=fmaf(win[k+3],w,a3); }
        B4[0]+=a0; B4[1]+=a1; B4[2]+=a2; B4[3]+=a3;
#pragma unroll
        for (int k = 0; k < 10; k++) win[k] = h1p[(r0+k)*H3STR + c];
        a0=a1=a2=a3=0.f;
#pragma unroll
        for (int k = 0; k < 7; k++) { float w=G1W[k];
            a0=fmaf(win[k],w,a0); a1=fmaf(win[k+1],w,a1);
            a2=fmaf(win[k+2],w,a2); a3=fmaf(win[k+3],w,a3); }
        C4[0]+=a0; C4[1]+=a1; C4[2]+=a2; C4[3]+=a3;
    }

    /* ---- phase 4: stencils (6-row shared loads) + pointwise + reductions ---- */
    float gxi4[4], gyi4[4], lapi4[4], xv4[4];
    {
        float xr[6][3];
#pragma unroll
        for (int k = 0; k < 6; k++) {
            int pp = (r0+8+k)*RAW_W + (c+11);
            xr[k][0]=s_xi[pp]; xr[k][1]=s_xi[pp+1]; xr[k][2]=s_xi[pp+2];
        }
#pragma unroll
        for (int j = 0; j < 4; j++) {
            float x00=xr[j][0],  x01=xr[j][1],  x02=xr[j][2];
            float x10=xr[j+1][0],x11=xr[j+1][1],x12=xr[j+1][2];
            float x20=xr[j+2][0],x21=xr[j+2][1],x22=xr[j+2][2];
            gxi4[j]  = (x02-x00) + 2.f*(x12-x10) + (x22-x20);
            gyi4[j]  = (x20-x00) + 2.f*(x21-x01) + (x22-x02);
            lapi4[j] = x01 + x21 + x10 + x12 - 4.f*x11;
            xv4[j]   = x11;
        }
    }
    float yr[6][3];
#pragma unroll
    for (int k = 0; k < 6; k++) {
        int pp = (r0+8+k)*RAW_W + (c+11);
        yr[k][0]=s_yp[pp]; yr[k][1]=s_yp[pp+1]; yr[k][2]=s_yp[pp+2];
    }

    float a_rc=0.f,a_nb=0.f,a_sxi=0.f,a_syp=0.f,a_ex=0.f,a_ey=0.f;
    float a_ntex=0.f,a_tex=0.f,a_nf=0.f,a_hf=0.f,a_ic=0.f;
    float a_nfb=0.f,a_lf=0.f,a_mid=0.f,a_syn=0.f;

#pragma unroll
    for (int j = 0; j < 4; j++) {
        size_t g = base + (size_t)(gy0 + r0 + j)*IMG_W + (gx0 + c);
        float wv = wmap[g], nv = npred[g], sv = nsyn[g];

        float y00=yr[j][0],  y01=yr[j][1],  y02=yr[j][2];
        float y10=yr[j+1][0],y11=yr[j+1][1],y12=yr[j+1][2];
        float y20=yr[j+2][0],y21=yr[j+2][1],y22=yr[j+2][2];

        float gxp_ = (y02-y00) + 2.f*(y12-y10) + (y22-y20);
        float gyp_ = (y20-y00) + 2.f*(y21-y01) + (y22-y02);
        float lapp = y01 + y21 + y10 + y12 - 4.f*y11;
        float gxi_ = gxi4[j], gyi_ = gyi4[j], lapi = lapi4[j];
        float xv = xv4[j], pv = y11;

        a_rc += fabsf(pv*wv - xv*wv);
        float gmi = fast_sqrtf(fmaf(gxi_,gxi_, fmaf(gyi_,gyi_, 1e-8f)));
        float gmp = fast_sqrtf(fmaf(gxp_,gxp_, fmaf(gyp_,gyp_, 1e-8f)));
        a_ex += fabsf(gxp_-gxi_);
        a_ey += fabsf(gyp_-gyi_);
        bool body = (xv > 0.15f) && (xv < 0.85f);
        bool flat = gmi < 0.03f;
        bool tex  = (gmi > 0.03f) && (gmi < 0.5f);
        if (body) {
            a_nb += 1.f; a_sxi += xv; a_syp += pv;
            if (j == 0) {   /* 4x row-subsampled quantile histograms */
                int bp = (int)(pv * (float)BINS); bp = bp < 0 ? 0 : (bp > BINS-1 ? BINS-1 : bp);
                int bx = (int)(xv * (float)BINS); bx = bx < 0 ? 0 : (bx > BINS-1 ? BINS-1 : bx);
                atomicAdd(&g_hist[bp], 1u);
                atomicAdd(&g_hist[BINS + bx], 1u);
            }
        }
        if (tex) { a_ntex += 1.f; a_tex += fabsf(gmp - gmi); }
        if (flat) {
            a_nf += 1.f;
            a_hf += fabsf(fabsf(lapp) - 0.3f*fabsf(lapi));
            a_ic += fmaxf(gmp - 2.0f*gmi, 0.f);
            if (body) {
                a_nfb += 1.f;
                a_lf  += fabsf(A4[j]);
                a_mid += fabsf(fabsf(C4[j]) - 0.3f*fabsf(B4[j]));
                a_syn += fabsf(nv - sv);
            }
        }
    }

    /* block reduction: warp shuffle -> plain STS partials -> 15-thread sum -> striped global */
    {
        float vals[NACC] = {a_rc,a_nb,a_sxi,a_syp,a_ex,a_ey,a_ntex,a_tex,
                            a_nf,a_hf,a_ic,a_nfb,a_lf,a_mid,a_syn};
        const int wid = tid >> 5;
#pragma unroll
        for (int i = 0; i < NACC; i++) {
            float v = vals[i];
#pragma unroll
            for (int off = 16; off; off >>= 1) v += __shfl_down_sync(0xffffffffu, v, off);
            if ((tid & 31) == 0) s_part[i][wid] = v;
        }
    }
    __syncthreads();
    {
        const int bid = blockIdx.x + blockIdx.y*GRID_X + blockIdx.z*(GRID_X*GRID_Y);
        const int stripe = bid & (NSTRIPE-1);
        if (tid < NACC) {
            float s = 0.f;
#pragma unroll
            for (int w = 0; w < 8; w++) s += s_part[tid][w];
            atomicAdd(&g_acc[stripe*NACC + tid], (double)s);
        }
    }

    /* ---- last-block finalize ---- */
    __threadfence();
    if (tid == 0) {
        unsigned int prev = atomicAdd(&g_done, 1u);
        s_islast = (prev == NBLOCKS-1) ? 1u : 0u;
    }
    __syncthreads();
    if (!s_islast) return;
    __threadfence();

    {
        __shared__ unsigned int pre_yp[257], pre_xi2[257];
        __shared__ float qv[8];
        __shared__ float s_fr[2];
        __shared__ double s_tot[NACC];
        const int t = tid;

        if (t < NACC) {
            double s = 0.0;
#pragma unroll
            for (int w = 0; w < NSTRIPE; w++) s += g_acc[w*NACC + t];
            s_tot[t] = s;
        }

        unsigned int syp = 0, sxi = 0;
#pragma unroll
        for (int i = 0; i < 16; i++) {
            syp += g_hist[t*16 + i];
            sxi += g_hist[BINS + t*16 + i];
        }
        pre_yp[t] = syp; pre_xi2[t] = sxi;
        if (t < 8) qv[t] = 0.f;
        __syncthreads();
        if (t == 0) {
            unsigned int run = 0;
            for (int i = 0; i < 256; i++) { unsigned int x = pre_yp[i]; pre_yp[i] = run; run += x; }
            pre_yp[256] = run;
            run = 0;
            for (int i = 0; i < 256; i++) { unsigned int x = pre_xi2[i]; pre_xi2[i] = run; run += x; }
            pre_xi2[256] = run;
        }
        __syncthreads();

        long long n = (long long)pre_xi2[256];
        long long ranks[4] = {0,0,0,0};
        float fr25 = 0.f, fr75 = 0.f;
        if (n > 0) {
            float pos25 = 0.25f * (float)(n-1);
            float pos75 = 0.75f * (float)(n-1);
            fr25 = pos25 - floorf(pos25);
            fr75 = pos75 - floorf(pos75);
            ranks[0] = (long long)floorf(pos25);
            ranks[1] = (long long)ceilf(pos25);
            ranks[2] = (long long)floorf(pos75);
            ranks[3] = (long long)ceilf(pos75);
        }
        if (t == 0) { s_fr[0] = fr25; s_fr[1] = fr75; }
        {
            long long cum = (long long)pre_yp[t];
            for (int i = 0; i < 16; i++) {
                unsigned int cnt = g_hist[t*16 + i];
#pragma unroll
                for (int j = 0; j < 4; j++) {
                    if (ranks[j] >= cum && ranks[j] < cum + (long long)cnt)
                        qv[j] = ((float)(t*16+i) + ((float)(ranks[j]-cum) + 0.5f)/(float)cnt) * (1.0f/(float)BINS);
                }
                cum += cnt;
            }
        }
        {
            long long cum = (long long)pre_xi2[t];
            for (int i = 0; i < 16; i++) {
                unsigned int cnt = g_hist[BINS + t*16 + i];
#pragma unroll
                for (int j = 0; j < 4; j++) {
                    if (ranks[j] >= cum && ranks[j] < cum + (long long)cnt)
                        qv[4+j] = ((float)(t*16+i) + ((float)(ranks[j]-cum) + 0.5f)/(float)cnt) * (1.0f/(float)BINS);
                }
                cum += cnt;
            }
        }
        __syncthreads();

        if (t == 0) {
            double nb      = s_tot[1];
            double rc      = s_tot[0] / NPIXD;
            double edge    = (s_tot[4] + s_tot[5]) / NPIXD;
            double mean_in = s_tot[2] / fmax(nb, 1.0);
            double mean_pr = s_tot[3] / fmax(nb, 1.0);
            float f25 = s_fr[0], f75 = s_fr[1];
            float q25p = qv[0]*(1.f-f25) + qv[1]*f25;
            float q75p = qv[2]*(1.f-f75) + qv[3]*f75;
            float q25i = qv[4]*(1.f-f25) + qv[5]*f25;
            float q75i = qv[6]*(1.f-f75) + qv[7]*f75;
            double dm   = mean_pr - mean_in;
            double dq25 = (double)q25p - (double)q25i;
            double dq75 = (double)q75p - (double)q75i;
            double hu   = dm*dm + 0.5*(dq25*dq25 + dq75*dq75);
            double loss_hu  = (nb > 4096.0) ? hu : 0.0;
            double ntex = s_tot[6];
            double loss_tex = (ntex > 100.0) ? s_tot[7]/fmax(ntex,1.0) : 0.0;
            double nf   = s_tot[8];
            double loss_hf  = (nf > 100.0) ? s_tot[9]/fmax(nf,1.0)  : 0.0;
            double loss_ic  = (nf > 100.0) ? s_tot[10]/fmax(nf,1.0) : 0.0;
            double nfb  = s_tot[11];
            double loss_lf  = (nfb > 100.0) ? s_tot[12]/fmax(nfb,1.0) : 0.0;
            double loss_mid = (nfb > 100.0) ? s_tot[13]/fmax(nfb,1.0) : 0.0;
            double loss_syn = (nfb > 100.0) ? s_tot[14]/fmax(nfb,1.0) : 0.0;
            double total = 2.0*rc + 1.5*loss_hu + 1.0*edge + 0.8*loss_tex
                         + 1.5*loss_hf + 0.8*loss_mid + 0.6*loss_lf
                         + 1.0*loss_syn + 0.8*loss_ic;
            out[0] = (float)total;
        }
        __syncthreads();

        /* self-clean for next graph replay */
        for (int i = t; i < 2*BINS; i += 256) g_hist[i] = 0u;
        for (int i = t; i < NSTRIPE*NACC; i += 256) g_acc[i] = 0.0;
        if (t == 0)  g_done = 0u;
    }
}

extern "C" void kernel_launch(void* const* d_in, const int* in_sizes, int n_in,
                              void* d_out, int out_size)
{
    (void)in_sizes; (void)n_in; (void)out_size;
    const float* ypred = (const float*)d_in[0];
    const float* npred = (const float*)d_in[1];
    const float* xi    = (const float*)d_in[2];
    /* d_in[3] = x_ip1 unused by the reference */
    const float* xmid  = (const float*)d_in[4];
    const float* wmap  = (const float*)d_in[5];
    const float* nsyn  = (const float*)d_in[6];

    cudaFuncSetAttribute(k_main, cudaFuncAttributeMaxDynamicSharedMemorySize,
                         SMEM_FLOATS * (int)sizeof(float));
    dim3 grid(GRID_X, GRID_Y, IMG_B);
    k_main<<<grid, 256, SMEM_FLOATS * sizeof(float)>>>(
        ypred, npred, xi, xmid, wmap, nsyn, (float*)d_out);
}